// round 2
// baseline (speedup 1.0000x reference)
#include <cuda_runtime.h>
#include <math.h>

#define B_  4
#define C_  64
#define O_  64
#define H_  128
#define W_  128
#define K2_ 9
#define OCOFF 27

// scratch: offsets/mask [b][ch=27][h][w], transposed weights
__device__ float g_off[B_ * OCOFF * H_ * W_];        // 1,769,472 floats
__device__ float g_wt [K2_ * C_ * O_];               // w_def as [k][c][o]
__device__ float g_wo [K2_ * C_ * 32];               // w_off as [k][c][o(pad32)]

// ---------------------------------------------------------------------------
// Kernel 0: transpose weights into staging-friendly layout (tiny, one pass)
// ---------------------------------------------------------------------------
__global__ void prep_w_kernel(const float* __restrict__ w_off,
                              const float* __restrict__ w_def) {
    int i = blockIdx.x * 256 + threadIdx.x;
    if (i < K2_ * C_ * O_) {
        int k = i / (C_ * O_);
        int r = i % (C_ * O_);
        int c = r >> 6, o = r & 63;
        g_wt[i] = w_def[(o * C_ + c) * K2_ + k];
    }
    if (i < K2_ * C_ * 32) {
        int k = i / (C_ * 32);
        int r = i % (C_ * 32);
        int c = r >> 5, o = r & 31;
        g_wo[i] = (o < OCOFF) ? w_off[(o * C_ + c) * K2_ + k] : 0.f;
    }
}

// ---------------------------------------------------------------------------
// Kernel 1: offset/mask conv.  Block = (b, h, 64-px segment), 256 threads.
// Output tile: 27(32) o x 64 p.  Thread micro-tile: 2o x 4p.
// ---------------------------------------------------------------------------
__global__ __launch_bounds__(256) void offset_conv_kernel(
    const float* __restrict__ feat, const float* __restrict__ b_off) {
    int blk  = blockIdx.x;
    int wseg = blk & 1;
    int h    = (blk >> 1) & (H_ - 1);
    int b    = blk >> 8;
    int w0   = wseg * 64;
    int t    = threadIdx.x;

    __shared__ float s_x[C_ * 64];   // [c][p]
    __shared__ float s_w[C_ * 32];   // [c][o]

    const int to = t >> 4;   // 0..15 -> o base = to*2
    const int tp = t & 15;   // 0..15 -> p base = tp*4
    float acc[2][4] = {};

    for (int k = 0; k < K2_; k++) {
        int dy = k / 3 - 1, dx = k % 3 - 1;
        int hs = h + dy;
        __syncthreads();   // previous GEMM done reading tiles
        // stage shifted feat tile (coalesced along p)
        for (int i = t; i < C_ * 64; i += 256) {
            int c = i >> 6, p = i & 63;
            int ws = w0 + p + dx;
            float v = 0.f;
            if (hs >= 0 && hs < H_ && ws >= 0 && ws < W_)
                v = feat[((b * C_ + c) * H_ + hs) * W_ + ws];
            s_x[i] = v;
        }
        // stage weight tile (coalesced: g_wo is [k][c][o])
        for (int i = t; i < C_ * 32; i += 256)
            s_w[i] = g_wo[k * (C_ * 32) + i];
        __syncthreads();
#pragma unroll 8
        for (int c = 0; c < C_; c++) {
            float4 xv = *(const float4*)&s_x[c * 64 + tp * 4];
            float2 wv = *(const float2*)&s_w[c * 32 + to * 2];
            acc[0][0] += wv.x * xv.x; acc[0][1] += wv.x * xv.y;
            acc[0][2] += wv.x * xv.z; acc[0][3] += wv.x * xv.w;
            acc[1][0] += wv.y * xv.x; acc[1][1] += wv.y * xv.y;
            acc[1][2] += wv.y * xv.z; acc[1][3] += wv.y * xv.w;
        }
    }
    // epilogue: bias, sigmoid for mask channels (18..26), store to g_off
#pragma unroll
    for (int j = 0; j < 2; j++) {
        int o = to * 2 + j;
        if (o >= OCOFF) continue;
        float bb = b_off[o];
        bool is_mask = (o >= 18);
        float* dst = &g_off[((b * OCOFF + o) * H_ + h) * W_ + w0 + tp * 4];
#pragma unroll
        for (int q = 0; q < 4; q++) {
            float v = acc[j][q] + bb;
            if (is_mask) v = 1.f / (1.f + expf(-v));
            dst[q] = v;
        }
    }
}

// ---------------------------------------------------------------------------
// Kernel 2: fused deformable sampling + 64x576 contraction + bias + relu.
// Block = (b, h, 64-px segment), 256 threads.  Per tap:
//   - 64 threads precompute 4 gather indices + mask-folded bilinear weights
//   - all threads gather-sample cols tile [64c x 64p] into smem
//   - register GEMM: thread micro-tile 4o x 4p
// ---------------------------------------------------------------------------
__global__ __launch_bounds__(256) void deform_gemm_kernel(
    const float* __restrict__ x, const float* __restrict__ b_def,
    float* __restrict__ out) {
    int blk  = blockIdx.x;
    int wseg = blk & 1;
    int h    = (blk >> 1) & (H_ - 1);
    int b    = blk >> 8;
    int w0   = wseg * 64;
    int t    = threadIdx.x;

    __shared__ float s_cols[C_ * 64];   // [c][p]  16 KB
    __shared__ float s_w   [C_ * O_];   // [c][o]  16 KB
    __shared__ int   s_idx [64 * 4];    // per-pixel 4 corner indices
    __shared__ float s_wtc [64 * 4];    // per-pixel 4 corner weights (x mask)

    const int to = t >> 4;   // o base = to*4
    const int tp = t & 15;   // p base = tp*4
    float acc[4][4] = {};
    const float* xb = x + (size_t)b * C_ * H_ * W_;

    const int   sp = t & 63;     // sampling pixel
    const int   sc = t >> 6;     // sampling channel group base (0..3)

    for (int k = 0; k < K2_; k++) {
        __syncthreads();   // GEMM of previous tap done reading s_cols/s_w
        // ---- precompute gather indices + weights for this tap (64 threads)
        if (t < 64) {
            int p  = t;
            int dy = k / 3 - 1, dx = k % 3 - 1;
            int base = (b * OCOFF * H_ + h) * W_ + (w0 + p);
            float ox = g_off[base + (0 * 9 + k) * (H_ * W_)];
            float oy = g_off[base + (1 * 9 + k) * (H_ * W_)];
            float m  = g_off[base + (2 * 9 + k) * (H_ * W_)];
            float ys = (float)(h + dy) + oy;
            float xs = (float)(w0 + p + dx) + ox;
            float y0f = floorf(ys), x0f = floorf(xs);
            float wy1 = ys - y0f, wx1 = xs - x0f;
            int y0 = (int)y0f, x0 = (int)x0f;
#pragma unroll
            for (int cr = 0; cr < 4; cr++) {
                int oyc = cr >> 1, oxc = cr & 1;
                int yy = y0 + oyc, xx = x0 + oxc;
                float wgt = (oyc ? wy1 : 1.f - wy1) * (oxc ? wx1 : 1.f - wx1) * m;
                bool valid = (yy >= 0) & (yy < H_) & (xx >= 0) & (xx < W_);
                int yc = min(max(yy, 0), H_ - 1);
                int xc = min(max(xx, 0), W_ - 1);
                s_idx[p * 4 + cr] = yc * W_ + xc;
                s_wtc[p * 4 + cr] = valid ? wgt : 0.f;
            }
        }
        // ---- stage weight tile (coalesced: g_wt is [k][c][o])
        for (int i = t; i < C_ * O_; i += 256)
            s_w[i] = g_wt[k * (C_ * O_) + i];
        __syncthreads();
        // ---- gather-sample cols tile
        {
            int4   iv = *(const int4*)  &s_idx[sp * 4];
            float4 wv = *(const float4*)&s_wtc[sp * 4];
#pragma unroll
            for (int j = 0; j < 16; j++) {
                int c = sc + j * 4;
                const float* xc = xb + c * (H_ * W_);
                float v = wv.x * xc[iv.x] + wv.y * xc[iv.y] +
                          wv.z * xc[iv.z] + wv.w * xc[iv.w];
                s_cols[c * 64 + sp] = v;
            }
        }
        __syncthreads();
        // ---- register GEMM: acc[o][p] += w[c][o] * cols[c][p]
#pragma unroll 4
        for (int c = 0; c < C_; c++) {
            float4 xv = *(const float4*)&s_cols[c * 64 + tp * 4];
            float4 wv = *(const float4*)&s_w  [c * 64 + to * 4];
            acc[0][0] += wv.x * xv.x; acc[0][1] += wv.x * xv.y;
            acc[0][2] += wv.x * xv.z; acc[0][3] += wv.x * xv.w;
            acc[1][0] += wv.y * xv.x; acc[1][1] += wv.y * xv.y;
            acc[1][2] += wv.y * xv.z; acc[1][3] += wv.y * xv.w;
            acc[2][0] += wv.z * xv.x; acc[2][1] += wv.z * xv.y;
            acc[2][2] += wv.z * xv.z; acc[2][3] += wv.z * xv.w;
            acc[3][0] += wv.w * xv.x; acc[3][1] += wv.w * xv.y;
            acc[3][2] += wv.w * xv.z; acc[3][3] += wv.w * xv.w;
        }
    }
    // ---- epilogue: bias + relu, vectorized store
#pragma unroll
    for (int j = 0; j < 4; j++) {
        int o = to * 4 + j;
        float bb = b_def[o];
        float4 r;
        r.x = fmaxf(acc[j][0] + bb, 0.f);
        r.y = fmaxf(acc[j][1] + bb, 0.f);
        r.z = fmaxf(acc[j][2] + bb, 0.f);
        r.w = fmaxf(acc[j][3] + bb, 0.f);
        *(float4*)&out[((b * O_ + o) * H_ + h) * W_ + w0 + tp * 4] = r;
    }
}

// ---------------------------------------------------------------------------
extern "C" void kernel_launch(void* const* d_in, const int* in_sizes, int n_in,
                              void* d_out, int out_size) {
    const float* x     = (const float*)d_in[0];
    const float* feat  = (const float*)d_in[1];
    const float* w_off = (const float*)d_in[2];
    const float* b_off = (const float*)d_in[3];
    const float* w_def = (const float*)d_in[4];
    const float* b_def = (const float*)d_in[5];
    float* out = (float*)d_out;

    prep_w_kernel<<<(K2_ * C_ * O_ + 255) / 256, 256>>>(w_off, w_def);
    offset_conv_kernel<<<B_ * H_ * (W_ / 64), 256>>>(feat, b_off);
    deform_gemm_kernel<<<B_ * H_ * (W_ / 64), 256>>>(x, b_def, out);
}